// round 4
// baseline (speedup 1.0000x reference)
#include <cuda_runtime.h>
#include <cstddef>

// ---------------------------------------------------------------------------
// Problem constants (fixed by the dataset)
// ---------------------------------------------------------------------------
#define S_LEN 2048
#define BATCH 64
#define IN0   64
#define HID   128
#define GDIM  512          // 4*HID, PyTorch gate order: i, f, g, o
#define NL    6
#define MROWS (BATCH * S_LEN)   // 131072

// ---------------------------------------------------------------------------
// Static device scratch (no allocation allowed)
// ---------------------------------------------------------------------------
__device__ float g_xg  [(size_t)MROWS * GDIM];  // 256 MB: per-layer xg = seq @ Wih^T
__device__ float g_seq0[(size_t)MROWS * HID];   // 64 MB ping
__device__ float g_seq1[(size_t)MROWS * HID];   // 64 MB pong

typedef unsigned long long u64;

// ---------------------------------------------------------------------------
// f32x2 helpers (sm_103a packed fp32 pipe; ptxas never auto-fuses these)
// ---------------------------------------------------------------------------
__device__ __forceinline__ u64 pk2(float a, float b) {
    u64 r;
    unsigned ua = __float_as_uint(a), ub = __float_as_uint(b);
    asm("mov.b64 %0, {%1, %2};" : "=l"(r) : "r"(ua), "r"(ub));
    return r;
}
__device__ __forceinline__ u64 ffma2(u64 a, u64 b, u64 c) {
    u64 d;
    asm("fma.rn.f32x2 %0, %1, %2, %3;" : "=l"(d) : "l"(a), "l"(b), "l"(c));
    return d;
}
__device__ __forceinline__ float2 upk2(u64 v) {
    unsigned lo, hi;
    asm("mov.b64 {%0, %1}, %2;" : "=r"(lo), "=r"(hi) : "l"(v));
    return make_float2(__uint_as_float(lo), __uint_as_float(hi));
}

__device__ __forceinline__ float sigf(float x)   { return 1.0f / (1.0f + __expf(-x)); }
__device__ __forceinline__ float tanh_f(float x) { return 2.0f * sigf(2.0f * x) - 1.0f; }

// ---------------------------------------------------------------------------
// GEMM: g_xg[r][n] = sum_k A[r][k] * W[n][k]
//   A: (MROWS, K) row-major   (x for layer 0, g_seq0/g_seq1 otherwise)
//   W: (512, K)   row-major
// Tile 128(M) x 128(N), K-chunk 64. 256 threads, 8x8 micro-tile with
// interleaved mapping m = ty + 16*i, n = tx + 16*j so inner-loop LDS.128
// reads are conflict-free (row stride 68 floats = 17 x 16B units).
// ---------------------------------------------------------------------------
template<int K>
__global__ __launch_bounds__(256, 2)
void gemm_xg(const float* __restrict__ Ax, const float* __restrict__ W, int asel)
{
    const float* A = (asel == 1) ? g_seq0 : (asel == 2) ? g_seq1 : Ax;
    extern __shared__ float sm[];
    float* As = sm;             // 128 x 68
    float* Bs = sm + 128 * 68;  // 128 x 68
    const int tx = threadIdx.x & 15;
    const int ty = threadIdx.x >> 4;
    const int row0 = blockIdx.y * 128;
    const int col0 = blockIdx.x * 128;

    float acc[8][8];
#pragma unroll
    for (int i = 0; i < 8; i++)
#pragma unroll
        for (int j = 0; j < 8; j++) acc[i][j] = 0.0f;

    const int NCH = K / 64;
    for (int kc = 0; kc < NCH; kc++) {
        if (kc) __syncthreads();
        // Load 128x64 A tile and 128x64 W tile (coalesced float4 loads,
        // direct float4 stores into padded rows).
#pragma unroll
        for (int p = 0; p < 8; p++) {
            int idx = threadIdx.x + 256 * p;   // 0..2047
            int r = idx >> 4;                  // 0..127
            int q = idx & 15;                  // 0..15
            float4 av = *(const float4*)(A + (size_t)(row0 + r) * K + kc * 64 + 4 * q);
            *(float4*)(As + r * 68 + 4 * q) = av;
            float4 wv = *(const float4*)(W + (size_t)(col0 + r) * K + kc * 64 + 4 * q);
            *(float4*)(Bs + r * 68 + 4 * q) = wv;
        }
        __syncthreads();

        const float4* As4 = (const float4*)As;
        const float4* Bs4 = (const float4*)Bs;
        for (int kq = 0; kq < 16; kq++) {
            float4 b4[8];
#pragma unroll
            for (int j = 0; j < 8; j++) b4[j] = Bs4[(tx + 16 * j) * 17 + kq];
#pragma unroll
            for (int i = 0; i < 8; i++) {
                float4 a4 = As4[(ty + 16 * i) * 17 + kq];
#pragma unroll
                for (int j = 0; j < 8; j++) {
                    acc[i][j] = fmaf(a4.x, b4[j].x, acc[i][j]);
                    acc[i][j] = fmaf(a4.y, b4[j].y, acc[i][j]);
                    acc[i][j] = fmaf(a4.z, b4[j].z, acc[i][j]);
                    acc[i][j] = fmaf(a4.w, b4[j].w, acc[i][j]);
                }
            }
        }
    }

#pragma unroll
    for (int i = 0; i < 8; i++) {
        size_t rbase = (size_t)(row0 + ty + 16 * i) * GDIM + col0 + tx;
#pragma unroll
        for (int j = 0; j < 8; j++)
            g_xg[rbase + 16 * j] = acc[i][j];
    }
}

// ---------------------------------------------------------------------------
// Recurrent kernel: one CTA per batch row, 512 threads (one per gate row).
// Whh split: cols [0,64) in SMEM (row stride 66 floats -> conflict-free
// LDS.64: lane bank = 2l mod 32 per 16-lane phase), cols [64,128) pre-packed
// into 32 f32x2 registers per thread. h broadcast from SMEM, c in registers
// of threads 0..127. Biases folded into the per-step xg read.
// ---------------------------------------------------------------------------
#define SW_STRIDE 66
#define RECUR_SMEM ((512 * SW_STRIDE + 132 + 512) * 4)   // 137,744 B

__global__ __launch_bounds__(512, 1)
void lstm_recur(const float* __restrict__ Whh,   // (512,128) this layer
                const float* __restrict__ h0,    // (64,128) this layer
                const float* __restrict__ c0,    // (64,128) this layer
                const float* __restrict__ bih,   // (512)
                const float* __restrict__ bhh,   // (512)
                int osel,                        // 1 -> g_seq0, 2 -> g_seq1
                float* __restrict__ hT)          // (64,128) slice of output
{
    extern __shared__ float sm[];
    float* sW = sm;                          // 512 x 66  (Whh cols 0..63, u64-packed)
    float* sH = sm + 512 * SW_STRIDE;        // 132 (h, 16B-aligned)
    float* sG = sH + 132;                    // 512 (activated gates)
    const int g = threadIdx.x;               // gate row 0..511
    const int b = blockIdx.x;                // batch row
    float* seq_out = (osel == 1) ? g_seq0 : g_seq1;

    // --- load Whh cols [0,64) into SMEM, pre-paired for f32x2 ---
    {
        const float* wrow = Whh + g * HID;
        u64* dst = (u64*)(sW + g * SW_STRIDE);
#pragma unroll
        for (int q = 0; q < 16; q++) {
            float4 v = *(const float4*)(wrow + 4 * q);
            dst[2 * q]     = pk2(v.x, v.y);
            dst[2 * q + 1] = pk2(v.z, v.w);
        }
    }
    // --- Whh cols [64,128) into registers, pre-paired ---
    u64 wr2[32];
    {
        const float* wrow = Whh + g * HID + 64;
#pragma unroll
        for (int q = 0; q < 16; q++) {
            float4 v = *(const float4*)(wrow + 4 * q);
            wr2[2 * q]     = pk2(v.x, v.y);
            wr2[2 * q + 1] = pk2(v.z, v.w);
        }
    }
    const float biasg = bih[g] + bhh[g];
    const bool is_tanh = ((g >> 7) == 2);    // gates 256..383 are 'g' (tanh)

    float c = 0.0f, h = 0.0f;
    if (g < HID) {
        sH[g] = h0[b * HID + g];
        c = c0[b * HID + g];
    }
    __syncthreads();

    const float* xrow = g_xg + (size_t)b * S_LEN * GDIM;
    float* orow = seq_out + (size_t)b * S_LEN * HID;

    float xcur = xrow[g];
    for (int t = 0; t < S_LEN; t++) {
        // prefetch next step's xg (one coalesced LDG per thread)
        float xnext = (t + 1 < S_LEN) ? xrow[(size_t)(t + 1) * GDIM + g] : 0.0f;

        // gate[g] = xg + bias + dot(Whh[g], h)   (f32x2, two partial lanes)
        const u64* w2 = (const u64*)(sW + g * SW_STRIDE);
        const u64* h2 = (const u64*)sH;
        u64 acc = pk2(xcur + biasg, 0.0f);
#pragma unroll
        for (int q = 0; q < 32; q++) acc = ffma2(w2[q], h2[q], acc);       // k 0..63
#pragma unroll
        for (int q = 0; q < 32; q++) acc = ffma2(wr2[q], h2[32 + q], acc); // k 64..127
        float2 p = upk2(acc);
        float raw = p.x + p.y;
        sG[g] = is_tanh ? tanh_f(raw) : sigf(raw);
        __syncthreads();

        if (g < HID) {
            float iv = sG[g], fv = sG[g + 128], gv = sG[g + 256], ov = sG[g + 384];
            c = fv * c + iv * gv;
            h = ov * tanh_f(c);
            sH[g] = h;
            orow[(size_t)t * HID + g] = h;
        }
        __syncthreads();
        xcur = xnext;
    }

    if (g < HID) hT[b * HID + g] = h;
}

// ---------------------------------------------------------------------------
// Launch: per layer, GEMM (xg precompute) then recurrent scan. Ping-pong
// sequence buffers between layers. 12 launches total, all graph-capturable.
// ---------------------------------------------------------------------------
extern "C" void kernel_launch(void* const* d_in, const int* in_sizes, int n_in,
                              void* d_out, int out_size)
{
    const float* x    = (const float*)d_in[0];  // (64,2048,64)
    const float* h0   = (const float*)d_in[1];  // (6,64,128)
    const float* c0   = (const float*)d_in[2];  // (6,64,128)
    const float* Wih0 = (const float*)d_in[3];  // (512,64)
    const float* WihR = (const float*)d_in[4];  // (5,512,128)
    const float* Whh  = (const float*)d_in[5];  // (6,512,128)
    const float* bih  = (const float*)d_in[6];  // (6,512)
    const float* bhh  = (const float*)d_in[7];  // (6,512)
    float* out = (float*)d_out;                 // (6,64,128)

    const int GEMM_SMEM = 2 * 128 * 68 * 4;     // 69,632 B
    cudaFuncSetAttribute(gemm_xg<64>,  cudaFuncAttributeMaxDynamicSharedMemorySize, GEMM_SMEM);
    cudaFuncSetAttribute(gemm_xg<128>, cudaFuncAttributeMaxDynamicSharedMemorySize, GEMM_SMEM);
    cudaFuncSetAttribute(lstm_recur,   cudaFuncAttributeMaxDynamicSharedMemorySize, RECUR_SMEM);

    dim3 ggrid(4, 1024);   // N-tiles x M-tiles

    // layer 0: input x (K=64), recur writes g_seq0 (osel=1)
    gemm_xg<64><<<ggrid, 256, GEMM_SMEM>>>(x, Wih0, 0);
    lstm_recur<<<BATCH, 512, RECUR_SMEM>>>(Whh, h0, c0, bih, bhh, 1, out);

    int insel = 1;
    for (int l = 1; l < NL; l++) {
        int outsel = (insel == 1) ? 2 : 1;
        gemm_xg<128><<<ggrid, 256, GEMM_SMEM>>>(
            nullptr, WihR + (size_t)(l - 1) * GDIM * HID, insel);
        lstm_recur<<<BATCH, 512, RECUR_SMEM>>>(
            Whh + (size_t)l * GDIM * HID,
            h0 + l * BATCH * HID,
            c0 + l * BATCH * HID,
            bih + l * GDIM,
            bhh + l * GDIM,
            outsel,
            out + l * BATCH * HID);
        insel = outsel;
    }
}

// round 5
// speedup vs baseline: 1.2404x; 1.2404x over previous
#include <cuda_runtime.h>
#include <cstddef>

// ---------------------------------------------------------------------------
// Problem constants (fixed by the dataset)
// ---------------------------------------------------------------------------
#define S_LEN 2048
#define BATCH 64
#define IN0   64
#define HID   128
#define GDIM  512          // 4*HID, PyTorch gate order: i, f, g, o
#define NL    6
#define MROWS (BATCH * S_LEN)   // 131072

// ---------------------------------------------------------------------------
// Static device scratch (no allocation allowed)
// ---------------------------------------------------------------------------
__device__ float g_xg  [(size_t)MROWS * GDIM];  // 256 MB: per-layer xg = seq @ Wih^T
__device__ float g_seq0[(size_t)MROWS * HID];   // 64 MB ping
__device__ float g_seq1[(size_t)MROWS * HID];   // 64 MB pong

typedef unsigned long long u64;

// ---------------------------------------------------------------------------
// f32x2 helpers (sm_103a packed fp32 pipe; ptxas never auto-fuses these)
// ---------------------------------------------------------------------------
__device__ __forceinline__ u64 pk2(float a, float b) {
    u64 r;
    unsigned ua = __float_as_uint(a), ub = __float_as_uint(b);
    asm("mov.b64 %0, {%1, %2};" : "=l"(r) : "r"(ua), "r"(ub));
    return r;
}
__device__ __forceinline__ u64 ffma2(u64 a, u64 b, u64 c) {
    u64 d;
    asm("fma.rn.f32x2 %0, %1, %2, %3;" : "=l"(d) : "l"(a), "l"(b), "l"(c));
    return d;
}
__device__ __forceinline__ float2 upk2(u64 v) {
    unsigned lo, hi;
    asm("mov.b64 {%0, %1}, %2;" : "=r"(lo), "=r"(hi) : "l"(v));
    return make_float2(__uint_as_float(lo), __uint_as_float(hi));
}

__device__ __forceinline__ float sigf(float x)   { return 1.0f / (1.0f + __expf(-x)); }
__device__ __forceinline__ float tanh_f(float x) { return 2.0f * sigf(2.0f * x) - 1.0f; }

__device__ __forceinline__ unsigned sptr(const void* p) {
    return (unsigned)__cvta_generic_to_shared(p);
}

// ---------------------------------------------------------------------------
// GEMM: g_xg[r][n] = sum_k A[r][k] * W[n][k]   (unchanged from round 3)
// ---------------------------------------------------------------------------
template<int K>
__global__ __launch_bounds__(256, 2)
void gemm_xg(const float* __restrict__ Ax, const float* __restrict__ W, int asel)
{
    const float* A = (asel == 1) ? g_seq0 : (asel == 2) ? g_seq1 : Ax;
    extern __shared__ float sm[];
    float* As = sm;             // 128 x 68
    float* Bs = sm + 128 * 68;  // 128 x 68
    const int tx = threadIdx.x & 15;
    const int ty = threadIdx.x >> 4;
    const int row0 = blockIdx.y * 128;
    const int col0 = blockIdx.x * 128;

    float acc[8][8];
#pragma unroll
    for (int i = 0; i < 8; i++)
#pragma unroll
        for (int j = 0; j < 8; j++) acc[i][j] = 0.0f;

    const int NCH = K / 64;
    for (int kc = 0; kc < NCH; kc++) {
        if (kc) __syncthreads();
#pragma unroll
        for (int p = 0; p < 8; p++) {
            int idx = threadIdx.x + 256 * p;
            int r = idx >> 4;
            int q = idx & 15;
            float4 av = *(const float4*)(A + (size_t)(row0 + r) * K + kc * 64 + 4 * q);
            *(float4*)(As + r * 68 + 4 * q) = av;
            float4 wv = *(const float4*)(W + (size_t)(col0 + r) * K + kc * 64 + 4 * q);
            *(float4*)(Bs + r * 68 + 4 * q) = wv;
        }
        __syncthreads();

        const float4* As4 = (const float4*)As;
        const float4* Bs4 = (const float4*)Bs;
        for (int kq = 0; kq < 16; kq++) {
            float4 b4[8];
#pragma unroll
            for (int j = 0; j < 8; j++) b4[j] = Bs4[(tx + 16 * j) * 17 + kq];
#pragma unroll
            for (int i = 0; i < 8; i++) {
                float4 a4 = As4[(ty + 16 * i) * 17 + kq];
#pragma unroll
                for (int j = 0; j < 8; j++) {
                    acc[i][j] = fmaf(a4.x, b4[j].x, acc[i][j]);
                    acc[i][j] = fmaf(a4.y, b4[j].y, acc[i][j]);
                    acc[i][j] = fmaf(a4.z, b4[j].z, acc[i][j]);
                    acc[i][j] = fmaf(a4.w, b4[j].w, acc[i][j]);
                }
            }
        }
    }

#pragma unroll
    for (int i = 0; i < 8; i++) {
        size_t rbase = (size_t)(row0 + ty + 16 * i) * GDIM + col0 + tx;
#pragma unroll
        for (int j = 0; j < 8; j++)
            g_xg[rbase + 16 * j] = acc[i][j];
    }
}

// ---------------------------------------------------------------------------
// Recurrent kernel, cluster version.
//   grid = 128 CTAs, cluster (2,1,1): CTA pair {2b, 2b+1} handles batch row b.
//   Rank r owns h-indices [64r, 64r+64): its 256 threads each own one gate row
//   grow = gt*128 + 64r + j  (gt = tid>>6 in {i,f,g,o}, j = tid&63).
//   The full Whh row (128 floats) lives in 64 u64 registers per thread ->
//   zero SMEM weight traffic. h is double-buffered in SMEM; each step the
//   64 updater threads write their new h locally AND into the peer CTA's
//   buffer via DSMEM, then release-arrive on the peer's mbarrier (count=64).
//   Everyone acquire-waits the local mbarrier before reading the new buffer.
// ---------------------------------------------------------------------------
__global__ __launch_bounds__(256, 1) __cluster_dims__(2, 1, 1)
void lstm_recur2(const float* __restrict__ Whh,   // (512,128) this layer
                 const float* __restrict__ h0,    // (64,128)
                 const float* __restrict__ c0,    // (64,128)
                 const float* __restrict__ bih,   // (512)
                 const float* __restrict__ bhh,   // (512)
                 int osel,                        // 1 -> g_seq0, 2 -> g_seq1
                 float* __restrict__ hT)          // (64,128) slice of output
{
    __shared__ alignas(16) float sH[2][HID];   // double-buffered hidden state
    __shared__ float sG[256];                  // activated gates (this CTA's rows)
    __shared__ alignas(8) u64 mbar;

    const int tid = threadIdx.x;
    unsigned rank;
    asm("mov.u32 %0, %%cluster_ctarank;" : "=r"(rank));
    const int r = (int)rank;                   // 0 or 1
    const int b = blockIdx.x >> 1;             // batch row
    const int gt = tid >> 6;                   // gate: 0=i 1=f 2=g 3=o
    const int j  = tid & 63;
    const int grow = gt * HID + r * 64 + j;    // global gate row
    const int hidx = r * 64 + j;               // only meaningful for tid<64 path
    float* seq_out = (osel == 1) ? g_seq0 : g_seq1;

    // ---- remote (peer CTA) shared-memory addresses ----
    const unsigned peer = rank ^ 1u;
    unsigned lsh0 = sptr(&sH[0][0]);
    unsigned lsh1 = sptr(&sH[1][0]);
    unsigned lmb  = sptr(&mbar);
    unsigned psh0, psh1, pmb;
    asm("mapa.shared::cluster.u32 %0, %1, %2;" : "=r"(psh0) : "r"(lsh0), "r"(peer));
    asm("mapa.shared::cluster.u32 %0, %1, %2;" : "=r"(psh1) : "r"(lsh1), "r"(peer));
    asm("mapa.shared::cluster.u32 %0, %1, %2;" : "=r"(pmb)  : "r"(lmb),  "r"(peer));

    // ---- load this thread's full Whh row into 64 u64 registers ----
    u64 w2[64];
    {
        const float* wrow = Whh + (size_t)grow * HID;
#pragma unroll
        for (int q = 0; q < 32; q++) {
            float4 v = *(const float4*)(wrow + 4 * q);
            w2[2 * q]     = pk2(v.x, v.y);
            w2[2 * q + 1] = pk2(v.z, v.w);
        }
    }
    const float biasg = bih[grow] + bhh[grow];
    const bool is_tanh = (gt == 2);

    // ---- init: h0 into buffer 1 (read by step 0), c into updater registers ----
    if (tid < HID) sH[1][tid] = h0[b * HID + tid];
    float c = 0.0f, hlast = 0.0f;
    if (tid < 64) c = c0[b * HID + hidx];
    if (tid == 0) {
        asm volatile("mbarrier.init.shared.b64 [%0], 64;" :: "r"(lmb) : "memory");
    }
    __syncthreads();
    // all mbarrier inits + sH fills visible cluster-wide before any arrives
    asm volatile("barrier.cluster.arrive.aligned;" ::: "memory");
    asm volatile("barrier.cluster.wait.aligned;"   ::: "memory");

    const float* xrow = g_xg + ((size_t)b * S_LEN) * GDIM + grow;
    float* orow = seq_out + ((size_t)b * S_LEN) * HID;

    float xcur = xrow[0];
    for (int t = 0; t < S_LEN; t++) {
        float xnext = (t + 1 < S_LEN) ? xrow[(size_t)(t + 1) * GDIM] : 0.0f;

        // ---- matvec: gate[grow] = xg + bias + dot(Whh[grow], h_prev) ----
        const u64* h2 = (const u64*)sH[(t + 1) & 1];
        u64 a0 = pk2(xcur + biasg, 0.0f);
        u64 a1 = 0ull, a2 = 0ull, a3 = 0ull;
#pragma unroll
        for (int q = 0; q < 16; q++) {
            a0 = ffma2(w2[4 * q + 0], h2[4 * q + 0], a0);
            a1 = ffma2(w2[4 * q + 1], h2[4 * q + 1], a1);
            a2 = ffma2(w2[4 * q + 2], h2[4 * q + 2], a2);
            a3 = ffma2(w2[4 * q + 3], h2[4 * q + 3], a3);
        }
        float2 p0 = upk2(a0), p1 = upk2(a1), p2 = upk2(a2), p3 = upk2(a3);
        float raw = ((p0.x + p0.y) + (p1.x + p1.y)) + ((p2.x + p2.y) + (p3.x + p3.y));
        sG[tid] = is_tanh ? tanh_f(raw) : sigf(raw);
        __syncthreads();   // all 256 gates of this CTA visible

        // ---- cell/hidden update for this CTA's 64 h-indices ----
        if (tid < 64) {
            float iv = sG[tid], fv = sG[tid + 64], gv = sG[tid + 128], ov = sG[tid + 192];
            c = fv * c + iv * gv;
            float h = ov * tanh_f(c);
            hlast = h;
            const int w = t & 1;
            sH[w][hidx] = h;                                  // local copy
            unsigned pdst = ((w == 0) ? psh0 : psh1) + 4u * (unsigned)hidx;
            asm volatile("st.shared::cluster.f32 [%0], %1;" :: "r"(pdst), "f"(h) : "memory");
            orow[(size_t)t * HID + hidx] = h;                 // sequence output
            asm volatile("mbarrier.arrive.release.cluster.shared::cluster.b64 _, [%0];"
                         :: "r"(pmb) : "memory");
        }
        __syncthreads();   // local sH writes visible; sG safe to overwrite

        // ---- wait for peer's 64 h values for this step (acquire, cluster) ----
        {
            unsigned par = (unsigned)(t & 1);
            asm volatile(
                "{\n\t.reg .pred P;\n\t"
                "WL_%=:\n\t"
                "mbarrier.try_wait.parity.acquire.cluster.shared::cta.b64 P, [%0], %1, 0x989680;\n\t"
                "@!P bra WL_%=;\n\t}"
                :: "r"(lmb), "r"(par) : "memory");
        }
        xcur = xnext;
    }

    if (tid < 64) hT[b * HID + hidx] = hlast;
}

// ---------------------------------------------------------------------------
// Launch: per layer, GEMM (xg precompute) then recurrent scan.
// ---------------------------------------------------------------------------
extern "C" void kernel_launch(void* const* d_in, const int* in_sizes, int n_in,
                              void* d_out, int out_size)
{
    const float* x    = (const float*)d_in[0];  // (64,2048,64)
    const float* h0   = (const float*)d_in[1];  // (6,64,128)
    const float* c0   = (const float*)d_in[2];  // (6,64,128)
    const float* Wih0 = (const float*)d_in[3];  // (512,64)
    const float* WihR = (const float*)d_in[4];  // (5,512,128)
    const float* Whh  = (const float*)d_in[5];  // (6,512,128)
    const float* bih  = (const float*)d_in[6];  // (6,512)
    const float* bhh  = (const float*)d_in[7];  // (6,512)
    float* out = (float*)d_out;                 // (6,64,128)

    const int GEMM_SMEM = 2 * 128 * 68 * 4;     // 69,632 B
    cudaFuncSetAttribute(gemm_xg<64>,  cudaFuncAttributeMaxDynamicSharedMemorySize, GEMM_SMEM);
    cudaFuncSetAttribute(gemm_xg<128>, cudaFuncAttributeMaxDynamicSharedMemorySize, GEMM_SMEM);

    dim3 ggrid(4, 1024);   // N-tiles x M-tiles

    // layer 0: input x (K=64), recur writes g_seq0 (osel=1)
    gemm_xg<64><<<ggrid, 256, GEMM_SMEM>>>(x, Wih0, 0);
    lstm_recur2<<<2 * BATCH, 256>>>(Whh, h0, c0, bih, bhh, 1, out);

    int insel = 1;
    for (int l = 1; l < NL; l++) {
        int outsel = (insel == 1) ? 2 : 1;
        gemm_xg<128><<<ggrid, 256, GEMM_SMEM>>>(
            nullptr, WihR + (size_t)(l - 1) * GDIM * HID, insel);
        lstm_recur2<<<2 * BATCH, 256>>>(
            Whh + (size_t)l * GDIM * HID,
            h0 + l * BATCH * HID,
            c0 + l * BATCH * HID,
            bih + l * GDIM,
            bhh + l * GDIM,
            outsel,
            out + l * BATCH * HID);
        insel = outsel;
    }
}

// round 6
// speedup vs baseline: 1.2495x; 1.0073x over previous
#include <cuda_runtime.h>
#include <cstddef>

// ---------------------------------------------------------------------------
// Problem constants (fixed by the dataset)
// ---------------------------------------------------------------------------
#define S_LEN 2048
#define BATCH 64
#define IN0   64
#define HID   128
#define GDIM  512          // 4*HID, PyTorch gate order: i, f, g, o
#define NL    6
#define MROWS (BATCH * S_LEN)   // 131072

// ---------------------------------------------------------------------------
// Static device scratch (no allocation allowed)
// ---------------------------------------------------------------------------
__device__ float g_xg  [(size_t)MROWS * GDIM];  // 256 MB: per-layer xg = seq @ Wih^T
__device__ float g_seq0[(size_t)MROWS * HID];   // 64 MB ping
__device__ float g_seq1[(size_t)MROWS * HID];   // 64 MB pong

typedef unsigned long long u64;

// ---------------------------------------------------------------------------
// f32x2 helpers (sm_103a packed fp32 pipe; ptxas never auto-fuses these)
// ---------------------------------------------------------------------------
__device__ __forceinline__ u64 pk2(float a, float b) {
    u64 r;
    unsigned ua = __float_as_uint(a), ub = __float_as_uint(b);
    asm("mov.b64 %0, {%1, %2};" : "=l"(r) : "r"(ua), "r"(ub));
    return r;
}
__device__ __forceinline__ u64 ffma2(u64 a, u64 b, u64 c) {
    u64 d;
    asm("fma.rn.f32x2 %0, %1, %2, %3;" : "=l"(d) : "l"(a), "l"(b), "l"(c));
    return d;
}
__device__ __forceinline__ float2 upk2(u64 v) {
    unsigned lo, hi;
    asm("mov.b64 {%0, %1}, %2;" : "=r"(lo), "=r"(hi) : "l"(v));
    return make_float2(__uint_as_float(lo), __uint_as_float(hi));
}

__device__ __forceinline__ float sigf(float x)   { return 1.0f / (1.0f + __expf(-x)); }
__device__ __forceinline__ float tanh_f(float x) { return 2.0f * sigf(2.0f * x) - 1.0f; }

__device__ __forceinline__ unsigned sptr(const void* p) {
    return (unsigned)__cvta_generic_to_shared(p);
}

// ---------------------------------------------------------------------------
// GEMM: g_xg[r][n] = sum_k A[r][k] * W[n][k]
// Tile 128(M) x 128(N), K-chunk 64, 256 threads, 8x8 micro-tile.
// Inner product uses fma.rn.f32x2 paired along k (two k-columns per
// instruction); accumulator lanes are summed in the epilogue. acc = 64 u64
// registers -> occupancy 1, which is fine: 64 independent FMA chains keep
// the fma pipe saturated (pipe-bound at ~512 cyc/SMSP per kq vs ~274 issue).
// ---------------------------------------------------------------------------
template<int K>
__global__ __launch_bounds__(256, 1)
void gemm_xg(const float* __restrict__ Ax, const float* __restrict__ W, int asel)
{
    const float* A = (asel == 1) ? g_seq0 : (asel == 2) ? g_seq1 : Ax;
    extern __shared__ float sm[];
    float* As = sm;             // 128 x 68
    float* Bs = sm + 128 * 68;  // 128 x 68
    const int tx = threadIdx.x & 15;
    const int ty = threadIdx.x >> 4;
    const int row0 = blockIdx.y * 128;
    const int col0 = blockIdx.x * 128;

    u64 acc2[8][8];
#pragma unroll
    for (int i = 0; i < 8; i++)
#pragma unroll
        for (int j = 0; j < 8; j++) acc2[i][j] = 0ull;

    const int NCH = K / 64;
    for (int kc = 0; kc < NCH; kc++) {
        if (kc) __syncthreads();
#pragma unroll
        for (int p = 0; p < 8; p++) {
            int idx = threadIdx.x + 256 * p;
            int r = idx >> 4;
            int q = idx & 15;
            float4 av = *(const float4*)(A + (size_t)(row0 + r) * K + kc * 64 + 4 * q);
            *(float4*)(As + r * 68 + 4 * q) = av;
            float4 wv = *(const float4*)(W + (size_t)(col0 + r) * K + kc * 64 + 4 * q);
            *(float4*)(Bs + r * 68 + 4 * q) = wv;
        }
        __syncthreads();

        const ulonglong2* As2 = (const ulonglong2*)As;
        const ulonglong2* Bs2 = (const ulonglong2*)Bs;
        for (int kq = 0; kq < 16; kq++) {
            ulonglong2 b2[8];
#pragma unroll
            for (int j = 0; j < 8; j++) b2[j] = Bs2[(tx + 16 * j) * 17 + kq];
#pragma unroll
            for (int i = 0; i < 8; i++) {
                ulonglong2 a2 = As2[(ty + 16 * i) * 17 + kq];
#pragma unroll
                for (int j = 0; j < 8; j++) {
                    acc2[i][j] = ffma2(a2.x, b2[j].x, acc2[i][j]);
                    acc2[i][j] = ffma2(a2.y, b2[j].y, acc2[i][j]);
                }
            }
        }
    }

#pragma unroll
    for (int i = 0; i < 8; i++) {
        size_t rbase = (size_t)(row0 + ty + 16 * i) * GDIM + col0 + tx;
#pragma unroll
        for (int j = 0; j < 8; j++) {
            float2 p = upk2(acc2[i][j]);
            g_xg[rbase + 16 * j] = p.x + p.y;
        }
    }
}

// ---------------------------------------------------------------------------
// Recurrent kernel, cluster version (2 CTAs per batch row, 128 SMs busy).
//   Rank r owns h-indices [64r,64r+64); its 256 threads each own one gate row
//   (grow = gt*128 + 64r + j) with the FULL 128-float Whh row in 64 u64 regs.
//   Per step: matvec (32 LDS.128 + 64 ffma2), one bar.sync, updater phase,
//   then a single mbarrier (count=128: 64 local release.cta arrives + 64
//   remote release.cluster arrives from the peer) replaces the second
//   bar.sync AND carries the cross-CTA h exchange ordering.
// ---------------------------------------------------------------------------
__global__ __launch_bounds__(256, 1) __cluster_dims__(2, 1, 1)
void lstm_recur2(const float* __restrict__ Whh,   // (512,128) this layer
                 const float* __restrict__ h0,    // (64,128)
                 const float* __restrict__ c0,    // (64,128)
                 const float* __restrict__ bih,   // (512)
                 const float* __restrict__ bhh,   // (512)
                 int osel,                        // 1 -> g_seq0, 2 -> g_seq1
                 float* __restrict__ hT)          // (64,128) slice of output
{
    __shared__ alignas(16) float sH[2][HID];   // double-buffered hidden state
    __shared__ float sG[256];                  // activated gates (this CTA's rows)
    __shared__ alignas(8) u64 mbar;

    const int tid = threadIdx.x;
    unsigned rank;
    asm("mov.u32 %0, %%cluster_ctarank;" : "=r"(rank));
    const int r = (int)rank;                   // 0 or 1
    const int b = blockIdx.x >> 1;             // batch row
    const int gt = tid >> 6;                   // gate: 0=i 1=f 2=g 3=o
    const int j  = tid & 63;
    const int grow = gt * HID + r * 64 + j;    // global gate row
    const int hidx = r * 64 + j;
    float* seq_out = (osel == 1) ? g_seq0 : g_seq1;

    // ---- remote (peer CTA) shared-memory addresses ----
    const unsigned peer = rank ^ 1u;
    unsigned lsh0 = sptr(&sH[0][0]);
    unsigned lsh1 = sptr(&sH[1][0]);
    unsigned lmb  = sptr(&mbar);
    unsigned psh0, psh1, pmb;
    asm("mapa.shared::cluster.u32 %0, %1, %2;" : "=r"(psh0) : "r"(lsh0), "r"(peer));
    asm("mapa.shared::cluster.u32 %0, %1, %2;" : "=r"(psh1) : "r"(lsh1), "r"(peer));
    asm("mapa.shared::cluster.u32 %0, %1, %2;" : "=r"(pmb)  : "r"(lmb),  "r"(peer));

    // ---- load this thread's full Whh row into 64 u64 registers ----
    u64 w2[64];
    {
        const float* wrow = Whh + (size_t)grow * HID;
#pragma unroll
        for (int q = 0; q < 32; q++) {
            float4 v = *(const float4*)(wrow + 4 * q);
            w2[2 * q]     = pk2(v.x, v.y);
            w2[2 * q + 1] = pk2(v.z, v.w);
        }
    }
    const float biasg = bih[grow] + bhh[grow];
    const bool is_tanh = (gt == 2);

    // ---- init: h0 into buffer 1 (read by step 0), c into updater regs ----
    if (tid < HID) sH[1][tid] = h0[b * HID + tid];
    float c = 0.0f, hlast = 0.0f;
    if (tid < 64) c = c0[b * HID + hidx];
    if (tid == 0) {
        asm volatile("mbarrier.init.shared.b64 [%0], 128;" :: "r"(lmb) : "memory");
    }
    __syncthreads();
    // all mbarrier inits + sH fills visible cluster-wide before any arrives
    asm volatile("barrier.cluster.arrive.aligned;" ::: "memory");
    asm volatile("barrier.cluster.wait.aligned;"   ::: "memory");

    const float* xrow = g_xg + ((size_t)b * S_LEN) * GDIM + grow;
    float* orow = seq_out + ((size_t)b * S_LEN) * HID;

    float xcur = xrow[0];
    for (int t = 0; t < S_LEN; t++) {
        float xnext = (t + 1 < S_LEN) ? xrow[(size_t)(t + 1) * GDIM] : 0.0f;

        // ---- matvec: gate[grow] = xg + bias + dot(Whh[grow], h_prev) ----
        const ulonglong2* h4 = (const ulonglong2*)sH[(t + 1) & 1];
        u64 a0 = pk2(xcur + biasg, 0.0f);
        u64 a1 = 0ull, a2 = 0ull, a3 = 0ull;
#pragma unroll
        for (int q = 0; q < 16; q++) {
            ulonglong2 hA = h4[2 * q];
            ulonglong2 hB = h4[2 * q + 1];
            a0 = ffma2(w2[4 * q + 0], hA.x, a0);
            a1 = ffma2(w2[4 * q + 1], hA.y, a1);
            a2 = ffma2(w2[4 * q + 2], hB.x, a2);
            a3 = ffma2(w2[4 * q + 3], hB.y, a3);
        }
        float2 p0 = upk2(a0), p1 = upk2(a1), p2 = upk2(a2), p3 = upk2(a3);
        float raw = ((p0.x + p0.y) + (p1.x + p1.y)) + ((p2.x + p2.y) + (p3.x + p3.y));
        sG[tid] = is_tanh ? tanh_f(raw) : sigf(raw);
        __syncthreads();   // all 256 gates of this CTA visible to updaters

        // ---- cell/hidden update for this CTA's 64 h-indices ----
        if (tid < 64) {
            float iv = sG[tid], fv = sG[tid + 64], gv = sG[tid + 128], ov = sG[tid + 192];
            c = fv * c + iv * gv;
            float h = ov * tanh_f(c);
            hlast = h;
            const int w = t & 1;
            sH[w][hidx] = h;                                  // local copy
            unsigned pdst = ((w == 0) ? psh0 : psh1) + 4u * (unsigned)hidx;
            asm volatile("st.shared::cluster.f32 [%0], %1;" :: "r"(pdst), "f"(h) : "memory");
            // release local (orders sG reads + local sH write for this CTA)
            asm volatile("mbarrier.arrive.release.cta.shared::cta.b64 _, [%0];"
                         :: "r"(lmb) : "memory");
            // release remote (orders the DSMEM h store for the peer)
            asm volatile("mbarrier.arrive.release.cluster.shared::cluster.b64 _, [%0];"
                         :: "r"(pmb) : "memory");
            orow[(size_t)t * HID + hidx] = h;                 // sequence output
        }

        // ---- single wait: 64 local + 64 peer arrives (acquire, cluster) ----
        {
            unsigned par = (unsigned)(t & 1);
            asm volatile(
                "{\n\t.reg .pred P;\n\t"
                "WL_%=:\n\t"
                "mbarrier.try_wait.parity.acquire.cluster.shared::cta.b64 P, [%0], %1, 0x989680;\n\t"
                "@!P bra WL_%=;\n\t}"
                :: "r"(lmb), "r"(par) : "memory");
        }
        xcur = xnext;
    }

    if (tid < 64) hT[b * HID + hidx] = hlast;
}

// ---------------------------------------------------------------------------
// Launch: per layer, GEMM (xg precompute) then recurrent scan.
// ---------------------------------------------------------------------------
extern "C" void kernel_launch(void* const* d_in, const int* in_sizes, int n_in,
                              void* d_out, int out_size)
{
    const float* x    = (const float*)d_in[0];  // (64,2048,64)
    const float* h0   = (const float*)d_in[1];  // (6,64,128)
    const float* c0   = (const float*)d_in[2];  // (6,64,128)
    const float* Wih0 = (const float*)d_in[3];  // (512,64)
    const float* WihR = (const float*)d_in[4];  // (5,512,128)
    const float* Whh  = (const float*)d_in[5];  // (6,512,128)
    const float* bih  = (const float*)d_in[6];  // (6,512)
    const float* bhh  = (const float*)d_in[7];  // (6,512)
    float* out = (float*)d_out;                 // (6,64,128)

    const int GEMM_SMEM = 2 * 128 * 68 * 4;     // 69,632 B
    cudaFuncSetAttribute(gemm_xg<64>,  cudaFuncAttributeMaxDynamicSharedMemorySize, GEMM_SMEM);
    cudaFuncSetAttribute(gemm_xg<128>, cudaFuncAttributeMaxDynamicSharedMemorySize, GEMM_SMEM);

    dim3 ggrid(4, 1024);   // N-tiles x M-tiles

    // layer 0: input x (K=64), recur writes g_seq0 (osel=1)
    gemm_xg<64><<<ggrid, 256, GEMM_SMEM>>>(x, Wih0, 0);
    lstm_recur2<<<2 * BATCH, 256>>>(Whh, h0, c0, bih, bhh, 1, out);

    int insel = 1;
    for (int l = 1; l < NL; l++) {
        int outsel = (insel == 1) ? 2 : 1;
        gemm_xg<128><<<ggrid, 256, GEMM_SMEM>>>(
            nullptr, WihR + (size_t)(l - 1) * GDIM * HID, insel);
        lstm_recur2<<<2 * BATCH, 256>>>(
            Whh + (size_t)l * GDIM * HID,
            h0 + l * BATCH * HID,
            c0 + l * BATCH * HID,
            bih + l * GDIM,
            bhh + l * GDIM,
            outsel,
            out + l * BATCH * HID);
        insel = outsel;
    }
}